// round 11
// baseline (speedup 1.0000x reference)
#include <cuda_runtime.h>
#include <cuda_fp16.h>
#include <cstdint>
#include <math.h>

// ---------------- problem constants ----------------
#define NN    50000
#define F0    128
#define H0    4
#define HC0   256
#define HC1   64
#define EMAX  900000
#define AGGW  8

// ---------------- scratch ----------------
__device__ __half g_lin0h[(size_t)NN * HC0];   // layer0 features, fp16
__device__ __half g_feath[(size_t)NN * HC0];   // relu(agg0+b0), fp16 (GEMM1 input)
__device__ __half g_lin1h[(size_t)NN * HC1];   // layer1 features, fp16
__device__ float  g_as0 [NN * H0];
__device__ float  g_ad0 [NN * H0];
__device__ float  g_as1 [NN];
__device__ float  g_ad1 [NN];
__device__ __align__(16) int g_deg [NN];       // zero at module load; re-zeroed by k_place
__device__ __align__(16) int g_row [NN + 4];
__device__ int    g_rank[EMAX];
__device__ int    g_srcl[EMAX];

__device__ __forceinline__ float leaky02(float v) { return v > 0.0f ? v : 0.2f * v; }

__device__ __forceinline__ unsigned tf32_of(float x) {
    unsigned u;
    asm("cvt.rna.tf32.f32 %0, %1;" : "=r"(u) : "f"(x));
    return u;
}

__device__ __forceinline__ void edge_sd(const int* __restrict__ ei, int e, int E, int& s, int& d) {
    if (e < E) { s = ei[e]; d = ei[E + e]; } else { s = e - E; d = e - E; }
}

__device__ __forceinline__ void store2(float* p, float a, float b) {
    *(float2*)p = make_float2(a, b);
}
__device__ __forceinline__ void store2(__half* p, float a, float b) {
    *(__half2*)p = __floats2half2_rn(a, b);
}

// ---------------- CSR build (atomic-free placement; deg re-zeroed in place) ----------------
__global__ void k_hist(const int* __restrict__ ei, int E, int Etot, int T) {
    int t = blockIdx.x * blockDim.x + threadIdx.x;
    if (t >= T) return;
#pragma unroll
    for (int i = 0; i < 4; i++) {
        int e = t + i * T;
        if (e < Etot) {
            int s, d; edge_sd(ei, e, E, s, d);
            g_rank[e] = atomicAdd(&g_deg[d], 1);
        }
    }
}
__global__ void k_scan() {
    __shared__ int ssum[1024];
    const int t  = threadIdx.x;
    const int CH = 52;
    const int beg = t * CH;
    int s = 0;
    if (beg < NN) {
#pragma unroll
        for (int j = 0; j < 13; j++) {
            int idx = beg + j * 4;
            if (idx < NN) {
                int4 v = *(const int4*)(g_deg + idx);
                s += v.x + v.y + v.z + v.w;
            }
        }
    }
    ssum[t] = s;
    __syncthreads();
    for (int o = 1; o < 1024; o <<= 1) {
        int v = (t >= o) ? ssum[t - o] : 0;
        __syncthreads();
        ssum[t] += v;
        __syncthreads();
    }
    int run = (t == 0) ? 0 : ssum[t - 1];
    if (beg < NN) {
#pragma unroll
        for (int j = 0; j < 13; j++) {
            int idx = beg + j * 4;
            if (idx < NN) {
                int4 v = *(const int4*)(g_deg + idx);
                int4 r;
                r.x = run; run += v.x;
                r.y = run; run += v.y;
                r.z = run; run += v.z;
                r.w = run; run += v.w;
                *(int4*)(g_row + idx) = r;
            }
        }
    }
    if (t == 0) g_row[NN] = ssum[1023];
}
// placement (no atomics) + re-zero g_deg for the next launch (idempotent stores;
// every dst has >=1 edge thanks to self-loops, so all of g_deg is covered)
__global__ void k_place(const int* __restrict__ ei, int E, int Etot, int T) {
    int t = blockIdx.x * blockDim.x + threadIdx.x;
    if (t >= T) return;
#pragma unroll
    for (int i = 0; i < 4; i++) {
        int e = t + i * T;
        if (e < Etot) {
            int s, d; edge_sd(ei, e, E, s, d);
            g_srcl[g_row[d] + g_rank[e]] = s;
            g_deg[d] = 0;
        }
    }
}

// ---------------- tf32 tensor-core GEMM + fused attention-coef epilogue ----------------
// A type templated: float (layer0) or __half (layer1). C type templated.
#define TBK 32
template<typename TI, typename TO>
__global__ void __launch_bounds__(256)
gemm_tf32(const TI* __restrict__ A, const float* __restrict__ B,
          TO* __restrict__ C, int M, int Nc, int K,
          const float* __restrict__ att_s, const float* __restrict__ att_d,
          float* __restrict__ as_out, float* __restrict__ ad_out)
{
    __shared__ unsigned As[128][TBK + 4];
    __shared__ unsigned Bs[64][TBK + 4];

    const int tid  = threadIdx.x;
    const int lane = tid & 31;
    const int warp = tid >> 5;
    const int g    = lane >> 2;
    const int q    = lane & 3;
    const int rowBase = blockIdx.x * 128;
    const int colBase = blockIdx.y * 64;
    const int warpRow = warp * 16;

    float acc[8][4];
#pragma unroll
    for (int t = 0; t < 8; t++)
#pragma unroll
        for (int j = 0; j < 4; j++) acc[t][j] = 0.f;

    for (int k0 = 0; k0 < K; k0 += TBK) {
        // ---- fill A tile (128 x 32) ----
        if constexpr (sizeof(TI) == 4) {
#pragma unroll
            for (int i = 0; i < 4; i++) {
                int f  = tid + i * 256;
                int r  = f >> 3;
                int c4 = (f & 7) * 4;
                float4 v = make_float4(0.f, 0.f, 0.f, 0.f);
                int gr = rowBase + r;
                if (gr < M) v = *(const float4*)((const float*)A + (size_t)gr * K + k0 + c4);
                As[r][c4+0] = tf32_of(v.x); As[r][c4+1] = tf32_of(v.y);
                As[r][c4+2] = tf32_of(v.z); As[r][c4+3] = tf32_of(v.w);
            }
        } else {
#pragma unroll
            for (int i = 0; i < 2; i++) {
                int f  = tid + i * 256;
                int r  = f >> 2;
                int c8 = (f & 3) * 8;
                uint4 u = make_uint4(0u, 0u, 0u, 0u);
                int gr = rowBase + r;
                if (gr < M) u = *(const uint4*)((const __half*)A + (size_t)gr * K + k0 + c8);
                const __half2* hp = (const __half2*)&u;
#pragma unroll
                for (int jj = 0; jj < 4; jj++) {
                    float2 fv = __half22float2(hp[jj]);
                    As[r][c8 + 2*jj]     = tf32_of(fv.x);
                    As[r][c8 + 2*jj + 1] = tf32_of(fv.y);
                }
            }
        }
        // ---- fill B tile (64 x 32) ----
#pragma unroll
        for (int i = 0; i < 2; i++) {
            int f  = tid + i * 256;
            int r  = f >> 3;
            int c4 = (f & 7) * 4;
            float4 v = *(const float4*)(B + (size_t)(colBase + r) * K + k0 + c4);
            Bs[r][c4+0] = tf32_of(v.x); Bs[r][c4+1] = tf32_of(v.y);
            Bs[r][c4+2] = tf32_of(v.z); Bs[r][c4+3] = tf32_of(v.w);
        }
        __syncthreads();

#pragma unroll
        for (int kk = 0; kk < TBK; kk += 8) {
            unsigned a0 = As[warpRow + g    ][kk + q];
            unsigned a1 = As[warpRow + g + 8][kk + q];
            unsigned a2 = As[warpRow + g    ][kk + q + 4];
            unsigned a3 = As[warpRow + g + 8][kk + q + 4];
#pragma unroll
            for (int t = 0; t < 8; t++) {
                unsigned b0 = Bs[t * 8 + g][kk + q];
                unsigned b1 = Bs[t * 8 + g][kk + q + 4];
                asm("mma.sync.aligned.m16n8k8.row.col.f32.tf32.tf32.f32 "
                    "{%0,%1,%2,%3}, {%4,%5,%6,%7}, {%8,%9}, {%0,%1,%2,%3};"
                    : "+f"(acc[t][0]), "+f"(acc[t][1]), "+f"(acc[t][2]), "+f"(acc[t][3])
                    : "r"(a0), "r"(a1), "r"(a2), "r"(a3), "r"(b0), "r"(b1));
            }
        }
        __syncthreads();
    }

    const int r0 = rowBase + warpRow + g;
    const int r1 = r0 + 8;
#pragma unroll
    for (int t = 0; t < 8; t++) {
        int col = colBase + t * 8 + q * 2;
        if (r0 < M) store2(C + (size_t)r0 * Nc + col, acc[t][0], acc[t][1]);
        if (r1 < M) store2(C + (size_t)r1 * Nc + col, acc[t][2], acc[t][3]);
    }

    {
        float ps0 = 0.f, pd0 = 0.f, ps1 = 0.f, pd1 = 0.f;
#pragma unroll
        for (int t = 0; t < 8; t++) {
            int col = colBase + t * 8 + q * 2;
            float s0 = att_s[col], s1 = att_s[col + 1];
            float d0 = att_d[col], d1 = att_d[col + 1];
            ps0 = fmaf(acc[t][0], s0, fmaf(acc[t][1], s1, ps0));
            pd0 = fmaf(acc[t][0], d0, fmaf(acc[t][1], d1, pd0));
            ps1 = fmaf(acc[t][2], s0, fmaf(acc[t][3], s1, ps1));
            pd1 = fmaf(acc[t][2], d0, fmaf(acc[t][3], d1, pd1));
        }
#pragma unroll
        for (int o = 1; o < 4; o <<= 1) {
            ps0 += __shfl_xor_sync(0xffffffffu, ps0, o);
            pd0 += __shfl_xor_sync(0xffffffffu, pd0, o);
            ps1 += __shfl_xor_sync(0xffffffffu, ps1, o);
            pd1 += __shfl_xor_sync(0xffffffffu, pd1, o);
        }
        const int Hh   = Nc >> 6;
        const int head = colBase >> 6;
        if (q == 0) {
            if (r0 < M) { as_out[r0 * Hh + head] = ps0; ad_out[r0 * Hh + head] = pd0; }
            if (r1 < M) { as_out[r1 * Hh + head] = ps1; ad_out[r1 * Hh + head] = pd1; }
        }
    }
}

// ---------------- aggregation layer 0: warp per dst, fp16, shfl src ids ----------------
__global__ void __launch_bounds__(AGGW * 32)
k_agg0(const float* __restrict__ b0)
{
    const int d    = (blockIdx.x * blockDim.x + threadIdx.x) >> 5;
    const int lane = threadIdx.x & 31;
    const int wl   = threadIdx.x >> 5;
    if (d >= NN) return;

    __shared__ float w_sm[AGGW][32 * 4];

    const int beg = g_row[d];
    const int n   = g_row[d + 1] - beg;
    const float4 ad = *(const float4*)(g_ad0 + d * 4);
    const int h     = lane >> 3;
    const int choff = lane * 8;

    float4 accA = make_float4(0.f, 0.f, 0.f, 0.f);
    float4 accB = make_float4(0.f, 0.f, 0.f, 0.f);
    float  den  = 0.f;

    for (int base = 0; base < n; base += 32) {
        const int m = min(32, n - base);
        __syncwarp();   // protect w_sm reuse across chunks

        // each lane loads its own src id (features can start before weights finish)
        int s_own = 0;
        if (lane < m) s_own = g_srcl[beg + base + lane];

        // feature pipeline: issue first P gathers immediately via shfl broadcast
        const int P = 4;
        uint4 v[P];
#pragma unroll
        for (int j = 0; j < P; j++)
            if (j < m) {
                int sj = __shfl_sync(0xffffffffu, s_own, j);
                v[j] = *(const uint4*)(g_lin0h + (size_t)sj * HC0 + choff);
            }

        // weight staging (overlaps with the feature gathers above)
        if (lane < m) {
            float4 a = *(const float4*)(g_as0 + s_own * 4);
            float4 w4;
            w4.x = __expf(leaky02(a.x + ad.x));
            w4.y = __expf(leaky02(a.y + ad.y));
            w4.z = __expf(leaky02(a.z + ad.z));
            w4.w = __expf(leaky02(a.w + ad.w));
            *(float4*)&w_sm[wl][lane * 4] = w4;
        }
        __syncwarp();

        for (int i = 0; i < m; i++) {
            float w = w_sm[wl][i * 4 + h];
            uint4 pk = v[i & (P - 1)];
            int nx = i + P;
            if (nx < m) {
                int sn = __shfl_sync(0xffffffffu, s_own, nx);
                v[i & (P - 1)] = *(const uint4*)(g_lin0h + (size_t)sn * HC0 + choff);
            }
            den += w;
            float2 f0 = __half22float2(*(__half2*)&pk.x);
            float2 f1 = __half22float2(*(__half2*)&pk.y);
            float2 f2 = __half22float2(*(__half2*)&pk.z);
            float2 f3 = __half22float2(*(__half2*)&pk.w);
            accA.x = fmaf(w, f0.x, accA.x);
            accA.y = fmaf(w, f0.y, accA.y);
            accA.z = fmaf(w, f1.x, accA.z);
            accA.w = fmaf(w, f1.y, accA.w);
            accB.x = fmaf(w, f2.x, accB.x);
            accB.y = fmaf(w, f2.y, accB.y);
            accB.z = fmaf(w, f3.x, accB.z);
            accB.w = fmaf(w, f3.y, accB.w);
        }
    }

    const float inv = 1.f / (den + 1e-16f);
    float4 bbA = *(const float4*)(b0 + choff);
    float4 bbB = *(const float4*)(b0 + choff + 4);
    union { uint4 u; __half2 hh[4]; } pk;
    pk.hh[0] = __floats2half2_rn(fmaxf(accA.x * inv + bbA.x, 0.f), fmaxf(accA.y * inv + bbA.y, 0.f));
    pk.hh[1] = __floats2half2_rn(fmaxf(accA.z * inv + bbA.z, 0.f), fmaxf(accA.w * inv + bbA.w, 0.f));
    pk.hh[2] = __floats2half2_rn(fmaxf(accB.x * inv + bbB.x, 0.f), fmaxf(accB.y * inv + bbB.y, 0.f));
    pk.hh[3] = __floats2half2_rn(fmaxf(accB.z * inv + bbB.z, 0.f), fmaxf(accB.w * inv + bbB.w, 0.f));
    *(uint4*)(g_feath + (size_t)d * HC0 + choff) = pk.u;
}

// ---------------- aggregation layer 1: half-warp per dst, fp16 features ----------------
__global__ void __launch_bounds__(256)
k_agg1(const float* __restrict__ b1, float* __restrict__ out)
{
    const int d    = (blockIdx.x * blockDim.x + threadIdx.x) >> 4;
    const int l    = threadIdx.x & 15;
    const int hwb  = threadIdx.x >> 4;
    const int hwl  = (threadIdx.x >> 4) & 1;
    const unsigned mask = 0xFFFFu << (hwl * 16);
    if (d >= NN) return;

    __shared__ int   s_sm[16][16];
    __shared__ float w_sm[16][16];

    const int beg = g_row[d];
    const int n   = g_row[d + 1] - beg;
    const float ad = g_ad1[d];
    const int choff = l * 4;

    float4 acc = make_float4(0.f, 0.f, 0.f, 0.f);
    float  den = 0.f;

    for (int base = 0; base < n; base += 16) {
        const int m = min(16, n - base);
        __syncwarp(mask);
        if (l < m) {
            int s = g_srcl[beg + base + l];
            s_sm[hwb][l] = s;
            w_sm[hwb][l] = __expf(leaky02(g_as1[s] + ad));
        }
        __syncwarp(mask);

        const int P = 4;
        uint2 v[P];
#pragma unroll
        for (int j = 0; j < P; j++)
            if (j < m)
                v[j] = *(const uint2*)(g_lin1h + (size_t)s_sm[hwb][j] * HC1 + choff);

        for (int i = 0; i < m; i++) {
            float w  = w_sm[hwb][i];
            uint2 pk = v[i & (P - 1)];
            int nx = i + P;
            if (nx < m)
                v[i & (P - 1)] = *(const uint2*)(g_lin1h + (size_t)s_sm[hwb][nx] * HC1 + choff);
            den += w;
            float2 f0 = __half22float2(*(__half2*)&pk.x);
            float2 f1 = __half22float2(*(__half2*)&pk.y);
            acc.x = fmaf(w, f0.x, acc.x);
            acc.y = fmaf(w, f0.y, acc.y);
            acc.z = fmaf(w, f1.x, acc.z);
            acc.w = fmaf(w, f1.y, acc.w);
        }
    }

    const float inv = 1.f / (den + 1e-16f);
    float4 bb = *(const float4*)(b1 + choff);
    float4 o;
    o.x = acc.x * inv + bb.x;
    o.y = acc.y * inv + bb.y;
    o.z = acc.z * inv + bb.z;
    o.w = acc.w * inv + bb.w;
    *(float4*)(out + (size_t)d * HC1 + choff) = o;
}

// ---------------- launch ----------------
extern "C" void kernel_launch(void* const* d_in, const int* in_sizes, int n_in,
                              void* d_out, int out_size)
{
    const float* x      = (const float*)d_in[0];
    const int*   ei     = (const int*)  d_in[1];
    const float* W0     = (const float*)d_in[2];
    const float* att_s0 = (const float*)d_in[3];
    const float* att_d0 = (const float*)d_in[4];
    const float* b0     = (const float*)d_in[5];
    const float* W1     = (const float*)d_in[6];
    const float* att_s1 = (const float*)d_in[7];
    const float* att_d1 = (const float*)d_in[8];
    const float* b1     = (const float*)d_in[9];

    const int E    = in_sizes[1] / 2;
    const int Etot = E + NN;

    __half *p_lin0h, *p_feath, *p_lin1h;
    float  *p_as0, *p_ad0, *p_as1, *p_ad1;
    cudaGetSymbolAddress((void**)&p_lin0h, g_lin0h);
    cudaGetSymbolAddress((void**)&p_feath, g_feath);
    cudaGetSymbolAddress((void**)&p_lin1h, g_lin1h);
    cudaGetSymbolAddress((void**)&p_as0,   g_as0);
    cudaGetSymbolAddress((void**)&p_ad0,   g_ad0);
    cudaGetSymbolAddress((void**)&p_as1,   g_as1);
    cudaGetSymbolAddress((void**)&p_ad1,   g_ad1);

    static cudaStream_t sB = nullptr;
    static cudaEvent_t  evFork = nullptr, evJoin = nullptr;
    if (sB == nullptr) {
        cudaStreamCreateWithFlags(&sB, cudaStreamNonBlocking);
        cudaEventCreateWithFlags(&evFork, cudaEventDisableTiming);
        cudaEventCreateWithFlags(&evJoin, cudaEventDisableTiming);
    }

    const int TB = 256;
    const int T4 = (Etot + 3) / 4;

    // ---- fork: CSR build on side stream, concurrent with GEMM0 ----
    cudaEventRecord(evFork, 0);
    cudaStreamWaitEvent(sB, evFork, 0);
    k_hist<<<(T4 + TB - 1) / TB, TB, 0, sB>>>(ei, E, Etot, T4);
    k_scan<<<1, 1024, 0, sB>>>();
    k_place<<<(T4 + TB - 1) / TB, TB, 0, sB>>>(ei, E, Etot, T4);
    cudaEventRecord(evJoin, sB);

    // ---- layer 0 GEMM (tf32, fp32 in, fp16 out) ----
    {
        dim3 grid((NN + 127) / 128, HC0 / 64);
        gemm_tf32<float, __half><<<grid, 256>>>(x, W0, p_lin0h, NN, HC0, F0,
                                                att_s0, att_d0, p_as0, p_ad0);
    }

    cudaStreamWaitEvent(0, evJoin, 0);
    k_agg0<<<(NN * 32 + AGGW * 32 - 1) / (AGGW * 32), AGGW * 32>>>(b0);

    // ---- layer 1 (tf32, fp16 in, fp16 out) ----
    {
        dim3 grid((NN + 127) / 128, HC1 / 64);
        gemm_tf32<__half, __half><<<grid, 256>>>(p_feath, W1, p_lin1h, NN, HC1, HC0,
                                                 att_s1, att_d1, p_as1, p_ad1);
    }
    k_agg1<<<(NN * 16 + TB - 1) / TB, TB>>>(b1, (float*)d_out);
}

// round 12
// speedup vs baseline: 1.0172x; 1.0172x over previous
#include <cuda_runtime.h>
#include <cuda_fp16.h>
#include <cstdint>
#include <math.h>

// ---------------- problem constants ----------------
#define NN    50000
#define F0    128
#define H0    4
#define HC0   256
#define HC1   64
#define EMAX  900000
#define AGGW  8

// ---------------- scratch ----------------
__device__ __half g_lin0h[(size_t)NN * HC0];   // layer0 features, fp16
__device__ __half g_feath[(size_t)NN * HC0];   // relu(agg0+b0), fp16 (GEMM1 input)
__device__ __half g_lin1h[(size_t)NN * HC1];   // layer1 features, fp16
__device__ float  g_as0 [NN * H0];
__device__ float  g_ad0 [NN * H0];
__device__ float  g_as1 [NN];
__device__ float  g_ad1 [NN];
__device__ __align__(16) int g_deg [NN];       // zero at module load; re-zeroed by k_place
__device__ __align__(16) int g_row [NN + 4];
__device__ int    g_rank[EMAX];
__device__ int    g_srcl[EMAX];

__device__ __forceinline__ float leaky02(float v) { return v > 0.0f ? v : 0.2f * v; }

__device__ __forceinline__ unsigned tf32_of(float x) {
    unsigned u;
    asm("cvt.rna.tf32.f32 %0, %1;" : "=r"(u) : "f"(x));
    return u;
}

__device__ __forceinline__ void edge_sd(const int* __restrict__ ei, int e, int E, int& s, int& d) {
    if (e < E) { s = ei[e]; d = ei[E + e]; } else { s = e - E; d = e - E; }
}

__device__ __forceinline__ void store2(float* p, float a, float b) {
    *(float2*)p = make_float2(a, b);
}
__device__ __forceinline__ void store2(__half* p, float a, float b) {
    *(__half2*)p = __floats2half2_rn(a, b);
}

// ---------------- CSR build (atomic-free placement; deg re-zeroed in place) ----------------
__global__ void k_hist(const int* __restrict__ ei, int E, int Etot, int T) {
    int t = blockIdx.x * blockDim.x + threadIdx.x;
    if (t >= T) return;
#pragma unroll
    for (int i = 0; i < 4; i++) {
        int e = t + i * T;
        if (e < Etot) {
            int s, d; edge_sd(ei, e, E, s, d);
            g_rank[e] = atomicAdd(&g_deg[d], 1);
        }
    }
}
__global__ void k_scan() {
    __shared__ int ssum[1024];
    const int t  = threadIdx.x;
    const int CH = 52;
    const int beg = t * CH;
    int s = 0;
    if (beg < NN) {
#pragma unroll
        for (int j = 0; j < 13; j++) {
            int idx = beg + j * 4;
            if (idx < NN) {
                int4 v = *(const int4*)(g_deg + idx);
                s += v.x + v.y + v.z + v.w;
            }
        }
    }
    ssum[t] = s;
    __syncthreads();
    for (int o = 1; o < 1024; o <<= 1) {
        int v = (t >= o) ? ssum[t - o] : 0;
        __syncthreads();
        ssum[t] += v;
        __syncthreads();
    }
    int run = (t == 0) ? 0 : ssum[t - 1];
    if (beg < NN) {
#pragma unroll
        for (int j = 0; j < 13; j++) {
            int idx = beg + j * 4;
            if (idx < NN) {
                int4 v = *(const int4*)(g_deg + idx);
                int4 r;
                r.x = run; run += v.x;
                r.y = run; run += v.y;
                r.z = run; run += v.z;
                r.w = run; run += v.w;
                *(int4*)(g_row + idx) = r;
            }
        }
    }
    if (t == 0) g_row[NN] = ssum[1023];
}
__global__ void k_place(const int* __restrict__ ei, int E, int Etot, int T) {
    int t = blockIdx.x * blockDim.x + threadIdx.x;
    if (t >= T) return;
#pragma unroll
    for (int i = 0; i < 4; i++) {
        int e = t + i * T;
        if (e < Etot) {
            int s, d; edge_sd(ei, e, E, s, d);
            g_srcl[g_row[d] + g_rank[e]] = s;
            g_deg[d] = 0;
        }
    }
}

// ---------------- tf32 tensor-core GEMM, permuted smem for vector LDS ----------------
// smem column permutation: perm(c) = (c&3)*8 + (c>>2)  (c in [0,32))
// => thread (g,q)'s fragments for kk in {16kh,16kh+8} are As[r][q*8 + 4kh .. +3] : one uint4.
#define TBK 32
#define SSTR (TBK + 4)     // 36 words = 144B; 144 % 128 == 16 -> conflict-free .128 phases
template<typename TI, typename TO>
__global__ void __launch_bounds__(256)
gemm_tf32(const TI* __restrict__ A, const float* __restrict__ B,
          TO* __restrict__ C, int M, int Nc, int K,
          const float* __restrict__ att_s, const float* __restrict__ att_d,
          float* __restrict__ as_out, float* __restrict__ ad_out)
{
    __shared__ __align__(16) unsigned As[128][SSTR];
    __shared__ __align__(16) unsigned Bs[64][SSTR];

    const int tid  = threadIdx.x;
    const int lane = tid & 31;
    const int warp = tid >> 5;
    const int g    = lane >> 2;
    const int q    = lane & 3;
    const int rowBase = blockIdx.x * 128;
    const int colBase = blockIdx.y * 64;
    const int warpRow = warp * 16;

    float acc[8][4];
#pragma unroll
    for (int t = 0; t < 8; t++)
#pragma unroll
        for (int j = 0; j < 4; j++) acc[t][j] = 0.f;

    for (int k0 = 0; k0 < K; k0 += TBK) {
        // ---- fill A tile (128 x 32), permuted ----
        if constexpr (sizeof(TI) == 4) {
#pragma unroll
            for (int i = 0; i < 4; i++) {
                int f  = tid + i * 256;
                int r  = f >> 3;
                int c4 = (f & 7) * 4;          // 4 consecutive c -> perm: j*8 + c4/4
                float4 v = make_float4(0.f, 0.f, 0.f, 0.f);
                int gr = rowBase + r;
                if (gr < M) v = *(const float4*)((const float*)A + (size_t)gr * K + k0 + c4);
                int pb = c4 >> 2;
                As[r][pb]      = tf32_of(v.x);
                As[r][pb + 8]  = tf32_of(v.y);
                As[r][pb + 16] = tf32_of(v.z);
                As[r][pb + 24] = tf32_of(v.w);
            }
        } else {
#pragma unroll
            for (int i = 0; i < 2; i++) {
                int f  = tid + i * 256;
                int r  = f >> 2;
                int c8 = (f & 3) * 8;          // 8 consecutive c
                uint4 u = make_uint4(0u, 0u, 0u, 0u);
                int gr = rowBase + r;
                if (gr < M) u = *(const uint4*)((const __half*)A + (size_t)gr * K + k0 + c8);
                const __half2* hp = (const __half2*)&u;
                int pb = c8 >> 2;              // c8/4
#pragma unroll
                for (int jj = 0; jj < 4; jj++) {
                    float2 fv = __half22float2(hp[jj]);
                    int c0 = 2 * jj;           // i-offset within the 8
                    int c1 = 2 * jj + 1;
                    As[r][(c0 & 3) * 8 + pb + (c0 >> 2)] = tf32_of(fv.x);
                    As[r][(c1 & 3) * 8 + pb + (c1 >> 2)] = tf32_of(fv.y);
                }
            }
        }
        // ---- fill B tile (64 x 32), permuted ----
#pragma unroll
        for (int i = 0; i < 2; i++) {
            int f  = tid + i * 256;
            int r  = f >> 3;
            int c4 = (f & 7) * 4;
            float4 v = *(const float4*)(B + (size_t)(colBase + r) * K + k0 + c4);
            int pb = c4 >> 2;
            Bs[r][pb]      = tf32_of(v.x);
            Bs[r][pb + 8]  = tf32_of(v.y);
            Bs[r][pb + 16] = tf32_of(v.z);
            Bs[r][pb + 24] = tf32_of(v.w);
        }
        __syncthreads();

        // ---- mainloop: 2 kk-steps per uint4 fragment load ----
#pragma unroll
        for (int kh = 0; kh < 2; kh++) {
            uint4 aLo = *(const uint4*)&As[warpRow + g    ][q * 8 + kh * 4];
            uint4 aHi = *(const uint4*)&As[warpRow + g + 8][q * 8 + kh * 4];
#pragma unroll
            for (int t = 0; t < 8; t++) {
                uint4 bv = *(const uint4*)&Bs[t * 8 + g][q * 8 + kh * 4];
                asm("mma.sync.aligned.m16n8k8.row.col.f32.tf32.tf32.f32 "
                    "{%0,%1,%2,%3}, {%4,%5,%6,%7}, {%8,%9}, {%0,%1,%2,%3};"
                    : "+f"(acc[t][0]), "+f"(acc[t][1]), "+f"(acc[t][2]), "+f"(acc[t][3])
                    : "r"(aLo.x), "r"(aHi.x), "r"(aLo.y), "r"(aHi.y), "r"(bv.x), "r"(bv.y));
                asm("mma.sync.aligned.m16n8k8.row.col.f32.tf32.tf32.f32 "
                    "{%0,%1,%2,%3}, {%4,%5,%6,%7}, {%8,%9}, {%0,%1,%2,%3};"
                    : "+f"(acc[t][0]), "+f"(acc[t][1]), "+f"(acc[t][2]), "+f"(acc[t][3])
                    : "r"(aLo.z), "r"(aHi.z), "r"(aLo.w), "r"(aHi.w), "r"(bv.z), "r"(bv.w));
            }
        }
        __syncthreads();
    }

    const int r0 = rowBase + warpRow + g;
    const int r1 = r0 + 8;
#pragma unroll
    for (int t = 0; t < 8; t++) {
        int col = colBase + t * 8 + q * 2;
        if (r0 < M) store2(C + (size_t)r0 * Nc + col, acc[t][0], acc[t][1]);
        if (r1 < M) store2(C + (size_t)r1 * Nc + col, acc[t][2], acc[t][3]);
    }

    {
        float ps0 = 0.f, pd0 = 0.f, ps1 = 0.f, pd1 = 0.f;
#pragma unroll
        for (int t = 0; t < 8; t++) {
            int col = colBase + t * 8 + q * 2;
            float s0 = att_s[col], s1 = att_s[col + 1];
            float d0 = att_d[col], d1 = att_d[col + 1];
            ps0 = fmaf(acc[t][0], s0, fmaf(acc[t][1], s1, ps0));
            pd0 = fmaf(acc[t][0], d0, fmaf(acc[t][1], d1, pd0));
            ps1 = fmaf(acc[t][2], s0, fmaf(acc[t][3], s1, ps1));
            pd1 = fmaf(acc[t][2], d0, fmaf(acc[t][3], d1, pd1));
        }
#pragma unroll
        for (int o = 1; o < 4; o <<= 1) {
            ps0 += __shfl_xor_sync(0xffffffffu, ps0, o);
            pd0 += __shfl_xor_sync(0xffffffffu, pd0, o);
            ps1 += __shfl_xor_sync(0xffffffffu, ps1, o);
            pd1 += __shfl_xor_sync(0xffffffffu, pd1, o);
        }
        const int Hh   = Nc >> 6;
        const int head = colBase >> 6;
        if (q == 0) {
            if (r0 < M) { as_out[r0 * Hh + head] = ps0; ad_out[r0 * Hh + head] = pd0; }
            if (r1 < M) { as_out[r1 * Hh + head] = ps1; ad_out[r1 * Hh + head] = pd1; }
        }
    }
}

// ---------------- aggregation layer 0: warp per dst, fp16, smem-staged ids/weights ----------------
__global__ void __launch_bounds__(AGGW * 32)
k_agg0(const float* __restrict__ b0)
{
    const int d    = (blockIdx.x * blockDim.x + threadIdx.x) >> 5;
    const int lane = threadIdx.x & 31;
    const int wl   = threadIdx.x >> 5;
    if (d >= NN) return;

    __shared__ int   s_sm[AGGW][32];
    __shared__ float w_sm[AGGW][32 * 4];

    const int beg = g_row[d];
    const int n   = g_row[d + 1] - beg;
    const float4 ad = *(const float4*)(g_ad0 + d * 4);
    const int h     = lane >> 3;
    const int choff = lane * 8;

    float4 accA = make_float4(0.f, 0.f, 0.f, 0.f);
    float4 accB = make_float4(0.f, 0.f, 0.f, 0.f);
    float  den  = 0.f;

    for (int base = 0; base < n; base += 32) {
        const int m = min(32, n - base);
        __syncwarp();
        if (lane < m) {
            int s = g_srcl[beg + base + lane];
            s_sm[wl][lane] = s;
            float4 a = *(const float4*)(g_as0 + s * 4);
            float4 w4;
            w4.x = __expf(leaky02(a.x + ad.x));
            w4.y = __expf(leaky02(a.y + ad.y));
            w4.z = __expf(leaky02(a.z + ad.z));
            w4.w = __expf(leaky02(a.w + ad.w));
            *(float4*)&w_sm[wl][lane * 4] = w4;
        }
        __syncwarp();

        const int P = 4;
        uint4 v[P];
#pragma unroll
        for (int j = 0; j < P; j++)
            if (j < m)
                v[j] = *(const uint4*)(g_lin0h + (size_t)s_sm[wl][j] * HC0 + choff);

        for (int i = 0; i < m; i++) {
            float w = w_sm[wl][i * 4 + h];
            uint4 pk = v[i & (P - 1)];
            int nx = i + P;
            if (nx < m)
                v[i & (P - 1)] = *(const uint4*)(g_lin0h + (size_t)s_sm[wl][nx] * HC0 + choff);
            den += w;
            float2 f0 = __half22float2(*(__half2*)&pk.x);
            float2 f1 = __half22float2(*(__half2*)&pk.y);
            float2 f2 = __half22float2(*(__half2*)&pk.z);
            float2 f3 = __half22float2(*(__half2*)&pk.w);
            accA.x = fmaf(w, f0.x, accA.x);
            accA.y = fmaf(w, f0.y, accA.y);
            accA.z = fmaf(w, f1.x, accA.z);
            accA.w = fmaf(w, f1.y, accA.w);
            accB.x = fmaf(w, f2.x, accB.x);
            accB.y = fmaf(w, f2.y, accB.y);
            accB.z = fmaf(w, f3.x, accB.z);
            accB.w = fmaf(w, f3.y, accB.w);
        }
    }

    const float inv = 1.f / (den + 1e-16f);
    float4 bbA = *(const float4*)(b0 + choff);
    float4 bbB = *(const float4*)(b0 + choff + 4);
    union { uint4 u; __half2 hh[4]; } pk;
    pk.hh[0] = __floats2half2_rn(fmaxf(accA.x * inv + bbA.x, 0.f), fmaxf(accA.y * inv + bbA.y, 0.f));
    pk.hh[1] = __floats2half2_rn(fmaxf(accA.z * inv + bbA.z, 0.f), fmaxf(accA.w * inv + bbA.w, 0.f));
    pk.hh[2] = __floats2half2_rn(fmaxf(accB.x * inv + bbB.x, 0.f), fmaxf(accB.y * inv + bbB.y, 0.f));
    pk.hh[3] = __floats2half2_rn(fmaxf(accB.z * inv + bbB.z, 0.f), fmaxf(accB.w * inv + bbB.w, 0.f));
    *(uint4*)(g_feath + (size_t)d * HC0 + choff) = pk.u;
}

// ---------------- aggregation layer 1: half-warp per dst, fp16 features ----------------
__global__ void __launch_bounds__(256)
k_agg1(const float* __restrict__ b1, float* __restrict__ out)
{
    const int d    = (blockIdx.x * blockDim.x + threadIdx.x) >> 4;
    const int l    = threadIdx.x & 15;
    const int hwb  = threadIdx.x >> 4;
    const int hwl  = (threadIdx.x >> 4) & 1;
    const unsigned mask = 0xFFFFu << (hwl * 16);
    if (d >= NN) return;

    __shared__ int   s_sm[16][16];
    __shared__ float w_sm[16][16];

    const int beg = g_row[d];
    const int n   = g_row[d + 1] - beg;
    const float ad = g_ad1[d];
    const int choff = l * 4;

    float4 acc = make_float4(0.f, 0.f, 0.f, 0.f);
    float  den = 0.f;

    for (int base = 0; base < n; base += 16) {
        const int m = min(16, n - base);
        __syncwarp(mask);
        if (l < m) {
            int s = g_srcl[beg + base + l];
            s_sm[hwb][l] = s;
            w_sm[hwb][l] = __expf(leaky02(g_as1[s] + ad));
        }
        __syncwarp(mask);

        const int P = 4;
        uint2 v[P];
#pragma unroll
        for (int j = 0; j < P; j++)
            if (j < m)
                v[j] = *(const uint2*)(g_lin1h + (size_t)s_sm[hwb][j] * HC1 + choff);

        for (int i = 0; i < m; i++) {
            float w  = w_sm[hwb][i];
            uint2 pk = v[i & (P - 1)];
            int nx = i + P;
            if (nx < m)
                v[i & (P - 1)] = *(const uint2*)(g_lin1h + (size_t)s_sm[hwb][nx] * HC1 + choff);
            den += w;
            float2 f0 = __half22float2(*(__half2*)&pk.x);
            float2 f1 = __half22float2(*(__half2*)&pk.y);
            acc.x = fmaf(w, f0.x, acc.x);
            acc.y = fmaf(w, f0.y, acc.y);
            acc.z = fmaf(w, f1.x, acc.z);
            acc.w = fmaf(w, f1.y, acc.w);
        }
    }

    const float inv = 1.f / (den + 1e-16f);
    float4 bb = *(const float4*)(b1 + choff);
    float4 o;
    o.x = acc.x * inv + bb.x;
    o.y = acc.y * inv + bb.y;
    o.z = acc.z * inv + bb.z;
    o.w = acc.w * inv + bb.w;
    *(float4*)(out + (size_t)d * HC1 + choff) = o;
}

// ---------------- launch ----------------
extern "C" void kernel_launch(void* const* d_in, const int* in_sizes, int n_in,
                              void* d_out, int out_size)
{
    const float* x      = (const float*)d_in[0];
    const int*   ei     = (const int*)  d_in[1];
    const float* W0     = (const float*)d_in[2];
    const float* att_s0 = (const float*)d_in[3];
    const float* att_d0 = (const float*)d_in[4];
    const float* b0     = (const float*)d_in[5];
    const float* W1     = (const float*)d_in[6];
    const float* att_s1 = (const float*)d_in[7];
    const float* att_d1 = (const float*)d_in[8];
    const float* b1     = (const float*)d_in[9];

    const int E    = in_sizes[1] / 2;
    const int Etot = E + NN;

    __half *p_lin0h, *p_feath, *p_lin1h;
    float  *p_as0, *p_ad0, *p_as1, *p_ad1;
    cudaGetSymbolAddress((void**)&p_lin0h, g_lin0h);
    cudaGetSymbolAddress((void**)&p_feath, g_feath);
    cudaGetSymbolAddress((void**)&p_lin1h, g_lin1h);
    cudaGetSymbolAddress((void**)&p_as0,   g_as0);
    cudaGetSymbolAddress((void**)&p_ad0,   g_ad0);
    cudaGetSymbolAddress((void**)&p_as1,   g_as1);
    cudaGetSymbolAddress((void**)&p_ad1,   g_ad1);

    static cudaStream_t sB = nullptr;
    static cudaEvent_t  evFork = nullptr, evJoin = nullptr;
    if (sB == nullptr) {
        cudaStreamCreateWithFlags(&sB, cudaStreamNonBlocking);
        cudaEventCreateWithFlags(&evFork, cudaEventDisableTiming);
        cudaEventCreateWithFlags(&evJoin, cudaEventDisableTiming);
    }

    const int TB = 256;
    const int T4 = (Etot + 3) / 4;

    // ---- fork: CSR build on side stream, concurrent with GEMM0 ----
    cudaEventRecord(evFork, 0);
    cudaStreamWaitEvent(sB, evFork, 0);
    k_hist<<<(T4 + TB - 1) / TB, TB, 0, sB>>>(ei, E, Etot, T4);
    k_scan<<<1, 1024, 0, sB>>>();
    k_place<<<(T4 + TB - 1) / TB, TB, 0, sB>>>(ei, E, Etot, T4);
    cudaEventRecord(evJoin, sB);

    // ---- layer 0 GEMM (tf32, fp32 in, fp16 out) ----
    {
        dim3 grid((NN + 127) / 128, HC0 / 64);
        gemm_tf32<float, __half><<<grid, 256>>>(x, W0, p_lin0h, NN, HC0, F0,
                                                att_s0, att_d0, p_as0, p_ad0);
    }

    cudaStreamWaitEvent(0, evJoin, 0);
    k_agg0<<<(NN * 32 + AGGW * 32 - 1) / (AGGW * 32), AGGW * 32>>>(b0);

    // ---- layer 1 (tf32, fp16 in, fp16 out) ----
    {
        dim3 grid((NN + 127) / 128, HC1 / 64);
        gemm_tf32<__half, __half><<<grid, 256>>>(p_feath, W1, p_lin1h, NN, HC1, HC0,
                                                 att_s1, att_d1, p_as1, p_ad1);
    }
    k_agg1<<<(NN * 16 + TB - 1) / TB, TB>>>(b1, (float*)d_out);
}

// round 13
// speedup vs baseline: 1.1331x; 1.1140x over previous
#include <cuda_runtime.h>
#include <cuda_fp16.h>
#include <cstdint>
#include <math.h>

// ---------------- problem constants ----------------
#define NN    50000
#define F0    128
#define H0    4
#define HC0   256
#define HC1   64
#define EMAX  900000
#define AGGW  8

// ---------------- scratch ----------------
__device__ __half g_lin0h[(size_t)NN * HC0];   // layer0 features, fp16
__device__ __half g_feath[(size_t)NN * HC0];   // relu(agg0+b0), fp16 (GEMM1 input)
__device__ __half g_lin1h[(size_t)NN * HC1];   // layer1 features, fp16
__device__ float  g_as0 [NN * H0];
__device__ float  g_ad0 [NN * H0];
__device__ float  g_as1 [NN];
__device__ float  g_ad1 [NN];
__device__ __align__(16) int g_deg [NN];       // zero at module load; re-zeroed by k_place
__device__ __align__(16) int g_row [NN + 4];
__device__ int    g_rank[EMAX];
__device__ int    g_srcl[EMAX];

__device__ __forceinline__ float leaky02(float v) { return v > 0.0f ? v : 0.2f * v; }

__device__ __forceinline__ unsigned pack_h2(float a, float b) {
    __half2 h = __floats2half2_rn(a, b);
    return *(unsigned*)&h;
}

__device__ __forceinline__ void edge_sd(const int* __restrict__ ei, int e, int E, int& s, int& d) {
    if (e < E) { s = ei[e]; d = ei[E + e]; } else { s = e - E; d = e - E; }
}

__device__ __forceinline__ void store2(__half* p, float a, float b) {
    *(__half2*)p = __floats2half2_rn(a, b);
}

// ---------------- CSR build (atomic-free placement; deg re-zeroed in place) ----------------
__global__ void k_hist(const int* __restrict__ ei, int E, int Etot, int T) {
    int t = blockIdx.x * blockDim.x + threadIdx.x;
    if (t >= T) return;
#pragma unroll
    for (int i = 0; i < 4; i++) {
        int e = t + i * T;
        if (e < Etot) {
            int s, d; edge_sd(ei, e, E, s, d);
            g_rank[e] = atomicAdd(&g_deg[d], 1);
        }
    }
}
__global__ void k_scan() {
    __shared__ int ssum[1024];
    const int t  = threadIdx.x;
    const int CH = 52;
    const int beg = t * CH;
    int s = 0;
    if (beg < NN) {
#pragma unroll
        for (int j = 0; j < 13; j++) {
            int idx = beg + j * 4;
            if (idx < NN) {
                int4 v = *(const int4*)(g_deg + idx);
                s += v.x + v.y + v.z + v.w;
            }
        }
    }
    ssum[t] = s;
    __syncthreads();
    for (int o = 1; o < 1024; o <<= 1) {
        int v = (t >= o) ? ssum[t - o] : 0;
        __syncthreads();
        ssum[t] += v;
        __syncthreads();
    }
    int run = (t == 0) ? 0 : ssum[t - 1];
    if (beg < NN) {
#pragma unroll
        for (int j = 0; j < 13; j++) {
            int idx = beg + j * 4;
            if (idx < NN) {
                int4 v = *(const int4*)(g_deg + idx);
                int4 r;
                r.x = run; run += v.x;
                r.y = run; run += v.y;
                r.z = run; run += v.z;
                r.w = run; run += v.w;
                *(int4*)(g_row + idx) = r;
            }
        }
    }
    if (t == 0) g_row[NN] = ssum[1023];
}
__global__ void k_place(const int* __restrict__ ei, int E, int Etot, int T) {
    int t = blockIdx.x * blockDim.x + threadIdx.x;
    if (t >= T) return;
#pragma unroll
    for (int i = 0; i < 4; i++) {
        int e = t + i * T;
        if (e < Etot) {
            int s, d; edge_sd(ei, e, E, s, d);
            g_srcl[g_row[d] + g_rank[e]] = s;
            g_deg[d] = 0;
        }
    }
}

// ---------------- fp16 tensor-core GEMM (m16n8k16, fp32 accum) + fused attn coefs ----------------
// C[M,Nc] = A[M,K] * B[Nc,K]^T. Block 128x64 (8 warps, warp = 16 rows x 64 cols).
// Smem tiles stored as half2 words; row stride 20 words (80B) -> conflict-free (4g+q distinct).
#define TBK 32
#define SW  20                       // half2-words per smem row (16 data + 4 pad)
template<typename TI>
__global__ void __launch_bounds__(256)
gemm_f16(const TI* __restrict__ A, const float* __restrict__ B,
         __half* __restrict__ C, int M, int Nc, int K,
         const float* __restrict__ att_s, const float* __restrict__ att_d,
         float* __restrict__ as_out, float* __restrict__ ad_out)
{
    __shared__ __align__(16) unsigned As[128][SW];
    __shared__ __align__(16) unsigned Bs[64][SW];

    const int tid  = threadIdx.x;
    const int lane = tid & 31;
    const int warp = tid >> 5;
    const int g    = lane >> 2;
    const int q    = lane & 3;
    const int rowBase = blockIdx.x * 128;
    const int colBase = blockIdx.y * 64;
    const int warpRow = warp * 16;

    float acc[8][4];
#pragma unroll
    for (int t = 0; t < 8; t++)
#pragma unroll
        for (int j = 0; j < 4; j++) acc[t][j] = 0.f;

    for (int k0 = 0; k0 < K; k0 += TBK) {
        // ---- fill A tile (128 x 32 halves) ----
        if constexpr (sizeof(TI) == 4) {
#pragma unroll
            for (int i = 0; i < 4; i++) {
                int f  = tid + i * 256;
                int r  = f >> 3;
                int c4 = (f & 7) * 4;            // float index
                float4 v = make_float4(0.f, 0.f, 0.f, 0.f);
                int gr = rowBase + r;
                if (gr < M) v = *(const float4*)((const float*)A + (size_t)gr * K + k0 + c4);
                As[r][(c4 >> 1)]     = pack_h2(v.x, v.y);
                As[r][(c4 >> 1) + 1] = pack_h2(v.z, v.w);
            }
        } else {
#pragma unroll
            for (int i = 0; i < 2; i++) {
                int f  = tid + i * 256;
                int r  = f >> 2;
                int c8 = (f & 3) * 8;            // half index
                uint4 u = make_uint4(0u, 0u, 0u, 0u);
                int gr = rowBase + r;
                if (gr < M) u = *(const uint4*)((const __half*)A + (size_t)gr * K + k0 + c8);
                *(uint4*)&As[r][c8 >> 1] = u;    // raw copy, no conversion
            }
        }
        // ---- fill B tile (64 x 32 halves) ----
#pragma unroll
        for (int i = 0; i < 2; i++) {
            int f  = tid + i * 256;
            int r  = f >> 3;
            int c4 = (f & 7) * 4;
            float4 v = *(const float4*)(B + (size_t)(colBase + r) * K + k0 + c4);
            Bs[r][(c4 >> 1)]     = pack_h2(v.x, v.y);
            Bs[r][(c4 >> 1) + 1] = pack_h2(v.z, v.w);
        }
        __syncthreads();

        // ---- mainloop: 2 kk-steps of k16 ----
#pragma unroll
        for (int kh = 0; kh < 2; kh++) {
            unsigned a0 = As[warpRow + g    ][kh * 8 + q];
            unsigned a1 = As[warpRow + g + 8][kh * 8 + q];
            unsigned a2 = As[warpRow + g    ][kh * 8 + q + 4];
            unsigned a3 = As[warpRow + g + 8][kh * 8 + q + 4];
#pragma unroll
            for (int t = 0; t < 8; t++) {
                unsigned b0 = Bs[t * 8 + g][kh * 8 + q];
                unsigned b1 = Bs[t * 8 + g][kh * 8 + q + 4];
                asm("mma.sync.aligned.m16n8k16.row.col.f32.f16.f16.f32 "
                    "{%0,%1,%2,%3}, {%4,%5,%6,%7}, {%8,%9}, {%0,%1,%2,%3};"
                    : "+f"(acc[t][0]), "+f"(acc[t][1]), "+f"(acc[t][2]), "+f"(acc[t][3])
                    : "r"(a0), "r"(a1), "r"(a2), "r"(a3), "r"(b0), "r"(b1));
            }
        }
        __syncthreads();
    }

    const int r0 = rowBase + warpRow + g;
    const int r1 = r0 + 8;
#pragma unroll
    for (int t = 0; t < 8; t++) {
        int col = colBase + t * 8 + q * 2;
        if (r0 < M) store2(C + (size_t)r0 * Nc + col, acc[t][0], acc[t][1]);
        if (r1 < M) store2(C + (size_t)r1 * Nc + col, acc[t][2], acc[t][3]);
    }

    // fused attention coefficients (BN==64 == one head), fp32
    {
        float ps0 = 0.f, pd0 = 0.f, ps1 = 0.f, pd1 = 0.f;
#pragma unroll
        for (int t = 0; t < 8; t++) {
            int col = colBase + t * 8 + q * 2;
            float s0 = att_s[col], s1 = att_s[col + 1];
            float d0 = att_d[col], d1 = att_d[col + 1];
            ps0 = fmaf(acc[t][0], s0, fmaf(acc[t][1], s1, ps0));
            pd0 = fmaf(acc[t][0], d0, fmaf(acc[t][1], d1, pd0));
            ps1 = fmaf(acc[t][2], s0, fmaf(acc[t][3], s1, ps1));
            pd1 = fmaf(acc[t][2], d0, fmaf(acc[t][3], d1, pd1));
        }
#pragma unroll
        for (int o = 1; o < 4; o <<= 1) {
            ps0 += __shfl_xor_sync(0xffffffffu, ps0, o);
            pd0 += __shfl_xor_sync(0xffffffffu, pd0, o);
            ps1 += __shfl_xor_sync(0xffffffffu, ps1, o);
            pd1 += __shfl_xor_sync(0xffffffffu, pd1, o);
        }
        const int Hh   = Nc >> 6;
        const int head = colBase >> 6;
        if (q == 0) {
            if (r0 < M) { as_out[r0 * Hh + head] = ps0; ad_out[r0 * Hh + head] = pd0; }
            if (r1 < M) { as_out[r1 * Hh + head] = ps1; ad_out[r1 * Hh + head] = pd1; }
        }
    }
}

// ---------------- aggregation layer 0: warp per dst, fp16, smem-staged ids/weights ----------------
__global__ void __launch_bounds__(AGGW * 32)
k_agg0(const float* __restrict__ b0)
{
    const int d    = (blockIdx.x * blockDim.x + threadIdx.x) >> 5;
    const int lane = threadIdx.x & 31;
    const int wl   = threadIdx.x >> 5;
    if (d >= NN) return;

    __shared__ int   s_sm[AGGW][32];
    __shared__ float w_sm[AGGW][32 * 4];

    const int beg = g_row[d];
    const int n   = g_row[d + 1] - beg;
    const float4 ad = *(const float4*)(g_ad0 + d * 4);
    const int h     = lane >> 3;
    const int choff = lane * 8;

    float4 accA = make_float4(0.f, 0.f, 0.f, 0.f);
    float4 accB = make_float4(0.f, 0.f, 0.f, 0.f);
    float  den  = 0.f;

    for (int base = 0; base < n; base += 32) {
        const int m = min(32, n - base);
        __syncwarp();
        if (lane < m) {
            int s = g_srcl[beg + base + lane];
            s_sm[wl][lane] = s;
            float4 a = *(const float4*)(g_as0 + s * 4);
            float4 w4;
            w4.x = __expf(leaky02(a.x + ad.x));
            w4.y = __expf(leaky02(a.y + ad.y));
            w4.z = __expf(leaky02(a.z + ad.z));
            w4.w = __expf(leaky02(a.w + ad.w));
            *(float4*)&w_sm[wl][lane * 4] = w4;
        }
        __syncwarp();

        const int P = 4;
        uint4 v[P];
#pragma unroll
        for (int j = 0; j < P; j++)
            if (j < m)
                v[j] = *(const uint4*)(g_lin0h + (size_t)s_sm[wl][j] * HC0 + choff);

        for (int i = 0; i < m; i++) {
            float w = w_sm[wl][i * 4 + h];
            uint4 pk = v[i & (P - 1)];
            int nx = i + P;
            if (nx < m)
                v[i & (P - 1)] = *(const uint4*)(g_lin0h + (size_t)s_sm[wl][nx] * HC0 + choff);
            den += w;
            float2 f0 = __half22float2(*(__half2*)&pk.x);
            float2 f1 = __half22float2(*(__half2*)&pk.y);
            float2 f2 = __half22float2(*(__half2*)&pk.z);
            float2 f3 = __half22float2(*(__half2*)&pk.w);
            accA.x = fmaf(w, f0.x, accA.x);
            accA.y = fmaf(w, f0.y, accA.y);
            accA.z = fmaf(w, f1.x, accA.z);
            accA.w = fmaf(w, f1.y, accA.w);
            accB.x = fmaf(w, f2.x, accB.x);
            accB.y = fmaf(w, f2.y, accB.y);
            accB.z = fmaf(w, f3.x, accB.z);
            accB.w = fmaf(w, f3.y, accB.w);
        }
    }

    const float inv = 1.f / (den + 1e-16f);
    float4 bbA = *(const float4*)(b0 + choff);
    float4 bbB = *(const float4*)(b0 + choff + 4);
    union { uint4 u; __half2 hh[4]; } pk;
    pk.hh[0] = __floats2half2_rn(fmaxf(accA.x * inv + bbA.x, 0.f), fmaxf(accA.y * inv + bbA.y, 0.f));
    pk.hh[1] = __floats2half2_rn(fmaxf(accA.z * inv + bbA.z, 0.f), fmaxf(accA.w * inv + bbA.w, 0.f));
    pk.hh[2] = __floats2half2_rn(fmaxf(accB.x * inv + bbB.x, 0.f), fmaxf(accB.y * inv + bbB.y, 0.f));
    pk.hh[3] = __floats2half2_rn(fmaxf(accB.z * inv + bbB.z, 0.f), fmaxf(accB.w * inv + bbB.w, 0.f));
    *(uint4*)(g_feath + (size_t)d * HC0 + choff) = pk.u;
}

// ---------------- aggregation layer 1: half-warp per dst, fp16 features ----------------
__global__ void __launch_bounds__(256)
k_agg1(const float* __restrict__ b1, float* __restrict__ out)
{
    const int d    = (blockIdx.x * blockDim.x + threadIdx.x) >> 4;
    const int l    = threadIdx.x & 15;
    const int hwb  = threadIdx.x >> 4;
    const int hwl  = (threadIdx.x >> 4) & 1;
    const unsigned mask = 0xFFFFu << (hwl * 16);
    if (d >= NN) return;

    __shared__ int   s_sm[16][16];
    __shared__ float w_sm[16][16];

    const int beg = g_row[d];
    const int n   = g_row[d + 1] - beg;
    const float ad = g_ad1[d];
    const int choff = l * 4;

    float4 acc = make_float4(0.f, 0.f, 0.f, 0.f);
    float  den = 0.f;

    for (int base = 0; base < n; base += 16) {
        const int m = min(16, n - base);
        __syncwarp(mask);
        if (l < m) {
            int s = g_srcl[beg + base + l];
            s_sm[hwb][l] = s;
            w_sm[hwb][l] = __expf(leaky02(g_as1[s] + ad));
        }
        __syncwarp(mask);

        const int P = 4;
        uint2 v[P];
#pragma unroll
        for (int j = 0; j < P; j++)
            if (j < m)
                v[j] = *(const uint2*)(g_lin1h + (size_t)s_sm[hwb][j] * HC1 + choff);

        for (int i = 0; i < m; i++) {
            float w  = w_sm[hwb][i];
            uint2 pk = v[i & (P - 1)];
            int nx = i + P;
            if (nx < m)
                v[i & (P - 1)] = *(const uint2*)(g_lin1h + (size_t)s_sm[hwb][nx] * HC1 + choff);
            den += w;
            float2 f0 = __half22float2(*(__half2*)&pk.x);
            float2 f1 = __half22float2(*(__half2*)&pk.y);
            acc.x = fmaf(w, f0.x, acc.x);
            acc.y = fmaf(w, f0.y, acc.y);
            acc.z = fmaf(w, f1.x, acc.z);
            acc.w = fmaf(w, f1.y, acc.w);
        }
    }

    const float inv = 1.f / (den + 1e-16f);
    float4 bb = *(const float4*)(b1 + choff);
    float4 o;
    o.x = acc.x * inv + bb.x;
    o.y = acc.y * inv + bb.y;
    o.z = acc.z * inv + bb.z;
    o.w = acc.w * inv + bb.w;
    *(float4*)(out + (size_t)d * HC1 + choff) = o;
}

// ---------------- launch ----------------
extern "C" void kernel_launch(void* const* d_in, const int* in_sizes, int n_in,
                              void* d_out, int out_size)
{
    const float* x      = (const float*)d_in[0];
    const int*   ei     = (const int*)  d_in[1];
    const float* W0     = (const float*)d_in[2];
    const float* att_s0 = (const float*)d_in[3];
    const float* att_d0 = (const float*)d_in[4];
    const float* b0     = (const float*)d_in[5];
    const float* W1     = (const float*)d_in[6];
    const float* att_s1 = (const float*)d_in[7];
    const float* att_d1 = (const float*)d_in[8];
    const float* b1     = (const float*)d_in[9];

    const int E    = in_sizes[1] / 2;
    const int Etot = E + NN;

    __half *p_lin0h, *p_feath, *p_lin1h;
    float  *p_as0, *p_ad0, *p_as1, *p_ad1;
    cudaGetSymbolAddress((void**)&p_lin0h, g_lin0h);
    cudaGetSymbolAddress((void**)&p_feath, g_feath);
    cudaGetSymbolAddress((void**)&p_lin1h, g_lin1h);
    cudaGetSymbolAddress((void**)&p_as0,   g_as0);
    cudaGetSymbolAddress((void**)&p_ad0,   g_ad0);
    cudaGetSymbolAddress((void**)&p_as1,   g_as1);
    cudaGetSymbolAddress((void**)&p_ad1,   g_ad1);

    static cudaStream_t sB = nullptr;
    static cudaEvent_t  evFork = nullptr, evJoin = nullptr;
    if (sB == nullptr) {
        cudaStreamCreateWithFlags(&sB, cudaStreamNonBlocking);
        cudaEventCreateWithFlags(&evFork, cudaEventDisableTiming);
        cudaEventCreateWithFlags(&evJoin, cudaEventDisableTiming);
    }

    const int TB = 256;
    const int T4 = (Etot + 3) / 4;

    // ---- fork: CSR build on side stream, concurrent with GEMM0 ----
    cudaEventRecord(evFork, 0);
    cudaStreamWaitEvent(sB, evFork, 0);
    k_hist<<<(T4 + TB - 1) / TB, TB, 0, sB>>>(ei, E, Etot, T4);
    k_scan<<<1, 1024, 0, sB>>>();
    k_place<<<(T4 + TB - 1) / TB, TB, 0, sB>>>(ei, E, Etot, T4);
    cudaEventRecord(evJoin, sB);

    // ---- layer 0 GEMM (fp16 MMA, fp32 in, fp16 out) ----
    {
        dim3 grid((NN + 127) / 128, HC0 / 64);
        gemm_f16<float><<<grid, 256>>>(x, W0, p_lin0h, NN, HC0, F0,
                                       att_s0, att_d0, p_as0, p_ad0);
    }

    cudaStreamWaitEvent(0, evJoin, 0);
    k_agg0<<<(NN * 32 + AGGW * 32 - 1) / (AGGW * 32), AGGW * 32>>>(b0);

    // ---- layer 1 (fp16 MMA, fp16 in, fp16 out) ----
    {
        dim3 grid((NN + 127) / 128, HC1 / 64);
        gemm_f16<__half><<<grid, 256>>>(p_feath, W1, p_lin1h, NN, HC1, HC0,
                                        att_s1, att_d1, p_as1, p_ad1);
    }
    k_agg1<<<(NN * 16 + TB - 1) / TB, TB>>>(b1, (float*)d_out);
}